// round 16
// baseline (speedup 1.0000x reference)
#include <cuda_runtime.h>
#include <cuda_fp16.h>
#include <math.h>
#include <stdint.h>

#define Bsz 4
#define Nn 1024
#define Dd 1024
#define Hh 8
#define HD 128
#define ROWS (Bsz * Nn)          // 4096
#define MAXNBR 192

// ---------------- scratch (static device globals; no allocation) ------------
__device__ float g_normed[ROWS * Dd];     // 16 MB  LN1 output
__device__ float g_h[ROWS * Dd];          // 16 MB  x + attn (residual stream)
__device__ float g_normed2[ROWS * Dd];    // 16 MB  LN2 output
__device__ float g_mlp1[ROWS * 4 * Dd];   // 64 MB  gelu(normed2 @ W1 + b1)
__device__ float g_w1t[4 * Dd * Dd];      // 16 MB  W1^T  [4096][1024]
__device__ float g_w2t[Dd * 4 * Dd];      // 16 MB  W2^T  [1024][4096]
__device__ int   g_nbr_idx[ROWS * MAXNBR];
__device__ int   g_nbr_cnt[ROWS];

// ---------------- LayerNorm: one block per row ------------------------------
__global__ void ln_kernel(const float* __restrict__ in,
                          const float* __restrict__ gamma,
                          const float* __restrict__ beta,
                          float* __restrict__ out) {
    int row = blockIdx.x;
    int tid = threadIdx.x;
    const float* p = in + (size_t)row * Dd;
    float s = 0.f, s2 = 0.f;
    for (int i = tid; i < Dd; i += 256) {
        float v = p[i];
        s += v; s2 += v * v;
    }
    __shared__ float rs[256], rs2[256];
    rs[tid] = s; rs2[tid] = s2;
    __syncthreads();
    for (int o = 128; o; o >>= 1) {
        if (tid < o) { rs[tid] += rs[tid + o]; rs2[tid] += rs2[tid + o]; }
        __syncthreads();
    }
    float mu = rs[0] * (1.f / Dd);
    float var = rs2[0] * (1.f / Dd) - mu * mu;
    float inv = rsqrtf(var + 1e-5f);
    float* q = out + (size_t)row * Dd;
    for (int i = tid; i < Dd; i += 256)
        q[i] = (p[i] - mu) * inv * gamma[i] + beta[i];
}

// ---------------- neighbor-list build: one block per (b,q) row --------------
__global__ void build_nbr_kernel(const int* __restrict__ adj) {
    int row = blockIdx.x;
    __shared__ int cnt;
    if (threadIdx.x == 0) cnt = 0;
    __syncthreads();
    const int* arow = adj + (size_t)row * Nn;
    for (int k = threadIdx.x; k < Nn; k += 256) {
        if (arow[k] > 0) {
            int pos = atomicAdd(&cnt, 1);
            if (pos < MAXNBR) g_nbr_idx[row * MAXNBR + pos] = k;
        }
    }
    __syncthreads();
    if (threadIdx.x == 0) g_nbr_cnt[row] = min(cnt, MAXNBR);
}

// ---------------- sparse attention (online softmax, single K pass) ----------
__global__ void attn_kernel(const float* __restrict__ x,
                            const float* __restrict__ stoich,
                            const float* __restrict__ gW,
                            const float* __restrict__ gb) {
    int row = blockIdx.x;
    int b = row >> 10;
    int tid = threadIdx.x;

    __shared__ float qrow[Dd];
    __shared__ float gate[MAXNBR];
    __shared__ int   nbr_s[MAXNBR];

    int cnt = g_nbr_cnt[row];

    ((float4*)qrow)[tid] = ((const float4*)(g_normed + (size_t)row * Dd))[tid];

    float st = stoich[row];
    for (int j = tid; j < cnt; j += 256) {
        int k = g_nbr_idx[row * MAXNBR + j];
        nbr_s[j] = k;
        gate[j] = 1.f / (1.f + expf(-(st * gW[k] + gb[k])));
    }
    __syncthreads();

    int wid = tid >> 5, lane = tid & 31;
    const float* base = g_normed + (size_t)b * Nn * Dd;
    float4 qv = ((const float4*)qrow)[wid * 32 + lane];

    const float scale = 0.08838834764831845f;  // 1/sqrt(128)
    float m = -INFINITY, Z = 0.f;
    float4 acc = make_float4(0.f, 0.f, 0.f, 0.f);

    for (int j = 0; j < cnt; j++) {
        int k = nbr_s[j];
        float4 kv = ((const float4*)(base + (size_t)k * Dd + wid * HD))[lane];
        float d = qv.x * kv.x + qv.y * kv.y + qv.z * kv.z + qv.w * kv.w;
#pragma unroll
        for (int o = 16; o; o >>= 1) d += __shfl_xor_sync(0xffffffffu, d, o);
        float s = d * scale * gate[j];
        float mNew = fmaxf(m, s);
        float corr = expf(m - mNew);
        float p = expf(s - mNew);
        Z = Z * corr + p;
        acc.x = acc.x * corr + p * kv.x;
        acc.y = acc.y * corr + p * kv.y;
        acc.z = acc.z * corr + p * kv.z;
        acc.w = acc.w * corr + p * kv.w;
        m = mNew;
    }
    float invZ = 1.f / Z;

    size_t off = (size_t)row * Dd + wid * HD + lane * 4;
    float4 xv = *(const float4*)(x + off);
    float4 o4 = make_float4(xv.x + acc.x * invZ, xv.y + acc.y * invZ,
                            xv.z + acc.z * invZ, xv.w + acc.w * invZ);
    *(float4*)(g_h + off) = o4;
}

// ---------------- transpose: out[c][r] = in[r][c], in is R x C ---------------
__global__ void transpose_kernel(const float* __restrict__ in,
                                 float* __restrict__ out, int R, int C) {
    __shared__ float t[32][33];
    int bx = blockIdx.x * 32, by = blockIdx.y * 32;
    int x = bx + threadIdx.x;
#pragma unroll
    for (int i = threadIdx.y; i < 32; i += 8)
        t[i][threadIdx.x] = in[(size_t)(by + i) * C + x];
    __syncthreads();
    int ox = by + threadIdx.x;
#pragma unroll
    for (int i = threadIdx.y; i < 32; i += 8)
        out[(size_t)(bx + i) * R + ox] = t[threadIdx.x][i];
}

// ================= FP16 tensor-core GEMM 128x128x32, m16n8k16 ================
__device__ __forceinline__ float gelu_exact(float v) {
    return 0.5f * v * (1.f + erff(v * 0.70710678118654752f));
}

__device__ __forceinline__ void mma_f16(float* c, const unsigned* a, const unsigned* b) {
    asm volatile(
        "mma.sync.aligned.m16n8k16.row.col.f32.f16.f16.f32 "
        "{%0,%1,%2,%3}, {%4,%5,%6,%7}, {%8,%9}, {%0,%1,%2,%3};"
        : "+f"(c[0]), "+f"(c[1]), "+f"(c[2]), "+f"(c[3])
        : "r"(a[0]), "r"(a[1]), "r"(a[2]), "r"(a[3]), "r"(b[0]), "r"(b[1]));
}

__device__ __forceinline__ unsigned pack_half2(float a, float b) {
    __half2 h = __floats2half2_rn(a, b);
    return *(unsigned*)&h;
}

// Tiles stored [row][k] as halves, row stride 40 halves (80 B) -> LDS conflict-free:
// frag word = r*20 + k/2, lanes (g,t) hit banks (g*20+t) mod 32, all distinct.
#define TLD 40   // halves per row

// A: [M][K] row-major fp32. Bt: [N][K] row-major fp32 (pre-transposed weight).
// C[m][n] = sum_k A[m][k]*Bt[n][k] + bias[n]; then gelu (ACT=1) or +res (ACT=0).
template <int ACT>
__global__ void __launch_bounds__(256)
hgemm_kernel(const float* __restrict__ A, const float* __restrict__ Bt,
             const float* __restrict__ bias, const float* __restrict__ res,
             float* __restrict__ C, int M, int N, int K) {
    __shared__ __half As[2][128 * TLD];   // 10240 B each
    __shared__ __half Bs[2][128 * TLD];

    int tid = threadIdx.x;
    int brow = blockIdx.y, bcol = blockIdx.x;
    int w = tid >> 5, lane = tid & 31;
    int wm = w & 1, wn = w >> 1;          // 2 x 4 warps
    int g = lane >> 2, t = lane & 3;

    // tile-load mapping: row = tid>>1 (0..127), k-half = (tid&1)*16
    int tr = tid >> 1;
    int tc = (tid & 1) * 16;
    const float* Ag = A + (size_t)(brow * 128 + tr) * K + tc;
    const float* Bg = Bt + (size_t)(bcol * 128 + tr) * K + tc;

    float acc[4][4][4] = {};
    float4 ra[4], rb[4];

    // prologue: load tile 0
#pragma unroll
    for (int i = 0; i < 4; i++) {
        ra[i] = *(const float4*)(Ag + 4 * i);
        rb[i] = *(const float4*)(Bg + 4 * i);
    }
#pragma unroll
    for (int i = 0; i < 4; i++) {
        uint2 ha = make_uint2(pack_half2(ra[i].x, ra[i].y), pack_half2(ra[i].z, ra[i].w));
        uint2 hb = make_uint2(pack_half2(rb[i].x, rb[i].y), pack_half2(rb[i].z, rb[i].w));
        *(uint2*)&As[0][tr * TLD + tc + 4 * i] = ha;
        *(uint2*)&Bs[0][tr * TLD + tc + 4 * i] = hb;
    }
    __syncthreads();

    int buf = 0;
    for (int k0 = 0; k0 < K; k0 += 32) {
        bool more = (k0 + 32 < K);
        if (more) {
#pragma unroll
            for (int i = 0; i < 4; i++) {
                ra[i] = *(const float4*)(Ag + k0 + 32 + 4 * i);
                rb[i] = *(const float4*)(Bg + k0 + 32 + 4 * i);
            }
        }

        const __half* as = As[buf];
        const __half* bs = Bs[buf];
#pragma unroll
        for (int ks = 0; ks < 2; ks++) {
            int kk = ks * 16 + 2 * t;
            unsigned af[4][4], bf[4][2];
#pragma unroll
            for (int mi = 0; mi < 4; mi++) {
                int r = wm * 64 + mi * 16 + g;
                af[mi][0] = *(const unsigned*)&as[r * TLD + kk];
                af[mi][1] = *(const unsigned*)&as[(r + 8) * TLD + kk];
                af[mi][2] = *(const unsigned*)&as[r * TLD + kk + 8];
                af[mi][3] = *(const unsigned*)&as[(r + 8) * TLD + kk + 8];
            }
#pragma unroll
            for (int ni = 0; ni < 4; ni++) {
                int n = wn * 32 + ni * 8 + g;
                bf[ni][0] = *(const unsigned*)&bs[n * TLD + kk];
                bf[ni][1] = *(const unsigned*)&bs[n * TLD + kk + 8];
            }
#pragma unroll
            for (int mi = 0; mi < 4; mi++)
#pragma unroll
                for (int ni = 0; ni < 4; ni++)
                    mma_f16(acc[mi][ni], af[mi], bf[ni]);
        }

        if (more) {
            int nb = buf ^ 1;
#pragma unroll
            for (int i = 0; i < 4; i++) {
                uint2 ha = make_uint2(pack_half2(ra[i].x, ra[i].y), pack_half2(ra[i].z, ra[i].w));
                uint2 hb = make_uint2(pack_half2(rb[i].x, rb[i].y), pack_half2(rb[i].z, rb[i].w));
                *(uint2*)&As[nb][tr * TLD + tc + 4 * i] = ha;
                *(uint2*)&Bs[nb][tr * TLD + tc + 4 * i] = hb;
            }
            __syncthreads();
            buf = nb;
        }
    }

    // epilogue: c0,c1 at (row0, col..col+1); c2,c3 at (row0+8, col..col+1)
#pragma unroll
    for (int mi = 0; mi < 4; mi++) {
        int row0 = brow * 128 + wm * 64 + mi * 16 + g;
#pragma unroll
        for (int ni = 0; ni < 4; ni++) {
            int col = bcol * 128 + wn * 32 + ni * 8 + 2 * t;
            float b0 = bias[col], b1 = bias[col + 1];
            float v0 = acc[mi][ni][0] + b0;
            float v1 = acc[mi][ni][1] + b1;
            float v2 = acc[mi][ni][2] + b0;
            float v3 = acc[mi][ni][3] + b1;
            if (ACT) {
                v0 = gelu_exact(v0); v1 = gelu_exact(v1);
                v2 = gelu_exact(v2); v3 = gelu_exact(v3);
            } else {
                const float* r0 = res + (size_t)row0 * N + col;
                const float* r1 = res + (size_t)(row0 + 8) * N + col;
                v0 += r0[0]; v1 += r0[1];
                v2 += r1[0]; v3 += r1[1];
            }
            float2* o0 = (float2*)(C + (size_t)row0 * N + col);
            float2* o1 = (float2*)(C + (size_t)(row0 + 8) * N + col);
            *o0 = make_float2(v0, v1);
            *o1 = make_float2(v2, v3);
        }
    }
}

// ---------------- launch -----------------------------------------------------
extern "C" void kernel_launch(void* const* d_in, const int* in_sizes, int n_in,
                              void* d_out, int out_size) {
    const float* x      = (const float*)d_in[0];
    const int*   adj    = (const int*)d_in[1];
    const float* stoich = (const float*)d_in[2];
    const float* ln1_g  = (const float*)d_in[3];
    const float* ln1_b  = (const float*)d_in[4];
    const float* ln2_g  = (const float*)d_in[5];
    const float* ln2_b  = (const float*)d_in[6];
    const float* W1     = (const float*)d_in[7];
    const float* b1     = (const float*)d_in[8];
    const float* W2     = (const float*)d_in[9];
    const float* b2     = (const float*)d_in[10];
    const float* gW     = (const float*)d_in[11];
    const float* gb     = (const float*)d_in[12];
    float* out = (float*)d_out;

    float *normed, *hbuf, *normed2, *mlp1, *w1t, *w2t;
    cudaGetSymbolAddress((void**)&normed,  g_normed);
    cudaGetSymbolAddress((void**)&hbuf,    g_h);
    cudaGetSymbolAddress((void**)&normed2, g_normed2);
    cudaGetSymbolAddress((void**)&mlp1,    g_mlp1);
    cudaGetSymbolAddress((void**)&w1t,     g_w1t);
    cudaGetSymbolAddress((void**)&w2t,     g_w2t);

    // 0. weight transposes (independent of the LN/attn chain)
    {
        dim3 blk(32, 8);
        dim3 g1(4 * Dd / 32, Dd / 32);       // W1 [1024][4096] -> w1t [4096][1024]
        transpose_kernel<<<g1, blk>>>(W1, w1t, Dd, 4 * Dd);
        dim3 g2(Dd / 32, 4 * Dd / 32);       // W2 [4096][1024] -> w2t [1024][4096]
        transpose_kernel<<<g2, blk>>>(W2, w2t, 4 * Dd, Dd);
    }
    // 1. LN1
    ln_kernel<<<ROWS, 256>>>(x, ln1_g, ln1_b, normed);
    // 2. neighbor lists
    build_nbr_kernel<<<ROWS, 256>>>(adj);
    // 3. sparse attention + residual -> g_h
    attn_kernel<<<ROWS, 256>>>(x, stoich, gW, gb);
    // 4. LN2
    ln_kernel<<<ROWS, 256>>>(hbuf, ln2_g, ln2_b, normed2);
    // 5. mlp1 = gelu(normed2 @ W1 + b1)   [4096 x 4096] K=1024
    {
        dim3 grid(4 * Dd / 128, ROWS / 128);
        hgemm_kernel<1><<<grid, 256>>>(normed2, w1t, b1, nullptr, mlp1,
                                       ROWS, 4 * Dd, Dd);
    }
    // 6. out = mlp1 @ W2 + b2 + g_h      [4096 x 1024] K=4096
    {
        dim3 grid(Dd / 128, ROWS / 128);
        hgemm_kernel<0><<<grid, 256>>>(mlp1, w2t, b2, hbuf, out,
                                       ROWS, Dd, 4 * Dd);
    }
}